// round 3
// baseline (speedup 1.0000x reference)
#include <cuda_runtime.h>
#include <cuda_bf16.h>
#include <math.h>

// ---------------------------------------------------------------------------
// SpectralDiscriminator: 5x SN-conv1x1 (+leaky 0.1) and 2x self-attention.
// B=4, N=64*64=4096. All ops are GEMMs over the channel dim.
//
// Scratch: static __device__ arrays (allocation-free, graph-capturable).
// ---------------------------------------------------------------------------

#define NPIX 4096
#define BATCH 4

__device__ float g_a1[BATCH * 64  * NPIX];                 //  4 MB
__device__ float g_a2[BATCH * 128 * NPIX];                 //  8 MB
__device__ float g_a3[BATCH * 256 * NPIX];                 // 16 MB
__device__ float g_q [BATCH * 64  * NPIX];                 //  4 MB
__device__ float g_kk[BATCH * 64  * NPIX];                 //  4 MB
__device__ float g_v [BATCH * 512 * NPIX];                 // 32 MB
__device__ float g_E [(size_t)BATCH * NPIX * NPIX];        // 256 MB
__device__ float g_t1[BATCH * 256 * NPIX];                 // 16 MB
__device__ float g_a4[BATCH * 512 * NPIX];                 // 32 MB
__device__ float g_t2[BATCH * 512 * NPIX];                 // 32 MB
__device__ float g_sig[8];                                 // 1/sigma per SN layer

// ---------------------------------------------------------------------------
// Spectral norm: sigma = ||W v|| with v = normalize(W^T u).
// (u2.(Wv) = ||t||^2 / (||t||+eps) with t = W v.)  One block per weight.
// ---------------------------------------------------------------------------
__global__ void snorm_kernel(const float* __restrict__ W, const float* __restrict__ u,
                             int O, int C, float* __restrict__ inv_sig) {
    __shared__ float v[512];
    __shared__ float red[256];
    int t = threadIdx.x;

    for (int c = t; c < C; c += 256) {
        float s = 0.f;
        for (int o = 0; o < O; o++) s += W[(size_t)o * C + c] * u[o];
        v[c] = s;
    }
    __syncthreads();

    float s = 0.f;
    for (int c = t; c < C; c += 256) s += v[c] * v[c];
    red[t] = s; __syncthreads();
    for (int off = 128; off > 0; off >>= 1) { if (t < off) red[t] += red[t + off]; __syncthreads(); }
    float vinv = 1.f / (sqrtf(red[0]) + 1e-12f);
    __syncthreads();

    for (int c = t; c < C; c += 256) v[c] *= vinv;
    __syncthreads();

    float s2 = 0.f;
    for (int o = t; o < O; o += 256) {
        float tv = 0.f;
        for (int c = 0; c < C; c++) tv += W[(size_t)o * C + c] * v[c];
        s2 += tv * tv;
    }
    red[t] = s2; __syncthreads();
    for (int off = 128; off > 0; off >>= 1) { if (t < off) red[t] += red[t + off]; __syncthreads(); }
    if (t == 0) {
        float S = red[0];
        float sigma = S / (sqrtf(S) + 1e-12f);
        inv_sig[0] = 1.f / sigma;
    }
}

// ---------------------------------------------------------------------------
// Generic tiled SGEMM.
//   logical: Cmat[M,N] = sum_k A[m,k] * B[k,n]
//   TA=0: A[m,k]=A[m*lda+k]   TA=1: A[m,k]=A[k*lda+m]
//   TB=0: B[k,n]=B[k*ldb+n]   TB=1: B[k,n]=B[n*ldb+k]
// Epilogues:
//   EPI=0: leaky( scale*acc + bias[m], 0.1 )      (SN conv layer)
//   EPI=1: acc + bias[m]                          (q/k/v conv)
//   EPI=2: acc                                    (energy)
//   EPI=3: gamma*acc + Res[m*ldc+n]               (attention out + residual)
// blockIdx.z = batch; per-batch strides sA/sB/sC/sR (elements).
// ---------------------------------------------------------------------------
#define BM 64
#define BN 64
#define BK 16

template<int TA, int TB, int EPI>
__global__ void __launch_bounds__(256)
gemm_k(const float* __restrict__ A, const float* __restrict__ B, float* __restrict__ Cmat,
       int M, int N, int K, int lda, int ldb, int ldc,
       size_t sA, size_t sB, size_t sC, size_t sR,
       const float* __restrict__ bias, const float* __restrict__ scaleP,
       const float* __restrict__ gammaP, const float* __restrict__ Res)
{
    __shared__ float As[BK][BM + 4];
    __shared__ float Bs[BK][BN + 4];

    int bz = blockIdx.z;
    A    += sA * bz;
    B    += sB * bz;
    Cmat += sC * bz;
    const float* R = (EPI == 3) ? (Res + sR * bz) : nullptr;

    int m0 = blockIdx.y * BM;
    int n0 = blockIdx.x * BN;
    int tid = threadIdx.x;
    int tx = tid & 15, ty = tid >> 4;

    float acc[4][4] = {};

    for (int k0 = 0; k0 < K; k0 += BK) {
        // ---- load A tile into As[k][m]
        if (TA == 0) {
            #pragma unroll
            for (int i = 0; i < 4; i++) {
                int e = tid + i * 256;
                int m = e >> 4, k = e & 15;
                int gm = m0 + m, gk = k0 + k;
                As[k][m] = (gm < M && gk < K) ? A[(size_t)gm * lda + gk] : 0.f;
            }
        } else {
            int k = tid >> 4;
            int m = (tid & 15) * 4;
            int gk = k0 + k;
            #pragma unroll
            for (int j = 0; j < 4; j++) {
                int gm = m0 + m + j;
                As[k][m + j] = (gm < M && gk < K) ? A[(size_t)gk * lda + gm] : 0.f;
            }
        }
        // ---- load B tile into Bs[k][n]
        if (TB == 0) {
            int k = tid >> 4;
            int n = (tid & 15) * 4;
            int gk = k0 + k;
            #pragma unroll
            for (int j = 0; j < 4; j++) {
                int gn = n0 + n + j;
                Bs[k][n + j] = (gn < N && gk < K) ? B[(size_t)gk * ldb + gn] : 0.f;
            }
        } else {
            int n = tid >> 2;
            int k = (tid & 3) * 4;
            int gn = n0 + n;
            #pragma unroll
            for (int j = 0; j < 4; j++) {
                int gk = k0 + k + j;
                Bs[k + j][n] = (gn < N && gk < K) ? B[(size_t)gn * ldb + gk] : 0.f;
            }
        }
        __syncthreads();

        #pragma unroll
        for (int kk = 0; kk < BK; kk++) {
            float a0 = As[kk][ty * 4 + 0];
            float a1 = As[kk][ty * 4 + 1];
            float a2 = As[kk][ty * 4 + 2];
            float a3 = As[kk][ty * 4 + 3];
            float b0 = Bs[kk][tx * 4 + 0];
            float b1 = Bs[kk][tx * 4 + 1];
            float b2 = Bs[kk][tx * 4 + 2];
            float b3 = Bs[kk][tx * 4 + 3];
            acc[0][0] += a0 * b0; acc[0][1] += a0 * b1; acc[0][2] += a0 * b2; acc[0][3] += a0 * b3;
            acc[1][0] += a1 * b0; acc[1][1] += a1 * b1; acc[1][2] += a1 * b2; acc[1][3] += a1 * b3;
            acc[2][0] += a2 * b0; acc[2][1] += a2 * b1; acc[2][2] += a2 * b2; acc[2][3] += a2 * b3;
            acc[3][0] += a3 * b0; acc[3][1] += a3 * b1; acc[3][2] += a3 * b2; acc[3][3] += a3 * b3;
        }
        __syncthreads();
    }

    float scale = (EPI == 0 && scaleP) ? *scaleP : 1.f;
    float gamma = (EPI == 3 && gammaP) ? *gammaP : 0.f;

    #pragma unroll
    for (int i = 0; i < 4; i++) {
        int gm = m0 + ty * 4 + i;
        if (gm >= M) continue;
        #pragma unroll
        for (int j = 0; j < 4; j++) {
            int gn = n0 + tx * 4 + j;
            if (gn >= N) continue;
            float v = acc[i][j];
            if (EPI == 0) {
                v = v * scale + bias[gm];
                v = (v > 0.f) ? v : 0.1f * v;
            } else if (EPI == 1) {
                v = v + bias[gm];
            } else if (EPI == 3) {
                v = gamma * v + R[(size_t)gm * ldc + gn];
            }
            Cmat[(size_t)gm * ldc + gn] = v;
        }
    }
}

// ---------------------------------------------------------------------------
// Row softmax over last axis (row length = NPIX), in place. One block per row.
// ---------------------------------------------------------------------------
__global__ void softmax_rows(float* __restrict__ E, int rowlen) {
    __shared__ float red[256];
    float* row = E + (size_t)blockIdx.x * rowlen;
    int t = threadIdx.x;

    float mx = -3.0e38f;
    for (int i = t; i < rowlen; i += 256) mx = fmaxf(mx, row[i]);
    red[t] = mx; __syncthreads();
    for (int off = 128; off > 0; off >>= 1) { if (t < off) red[t] = fmaxf(red[t], red[t + off]); __syncthreads(); }
    mx = red[0];
    __syncthreads();

    float sum = 0.f;
    for (int i = t; i < rowlen; i += 256) {
        float e = __expf(row[i] - mx);
        row[i] = e;
        sum += e;
    }
    red[t] = sum; __syncthreads();
    for (int off = 128; off > 0; off >>= 1) { if (t < off) red[t] += red[t + off]; __syncthreads(); }
    float inv = 1.f / red[0];

    for (int i = t; i < rowlen; i += 256) row[i] *= inv;
}

// ---------------------------------------------------------------------------
// kernel_launch
// ---------------------------------------------------------------------------
extern "C" void kernel_launch(void* const* d_in, const int* in_sizes, int n_in,
                              void* d_out, int out_size)
{
    const float* inp  = (const float*)d_in[0];
    const float* W1 = (const float*)d_in[1];  const float* b1 = (const float*)d_in[2];  const float* u1 = (const float*)d_in[3];
    const float* W2 = (const float*)d_in[4];  const float* b2 = (const float*)d_in[5];  const float* u2 = (const float*)d_in[6];
    const float* W3 = (const float*)d_in[7];  const float* b3 = (const float*)d_in[8];  const float* u3 = (const float*)d_in[9];
    const float* W4 = (const float*)d_in[10]; const float* b4 = (const float*)d_in[11]; const float* u4 = (const float*)d_in[12];
    const float* W5 = (const float*)d_in[13]; const float* b5 = (const float*)d_in[14]; const float* u5 = (const float*)d_in[15];
    const float* a1qW = (const float*)d_in[16]; const float* a1qb = (const float*)d_in[17];
    const float* a1kW = (const float*)d_in[18]; const float* a1kb = (const float*)d_in[19];
    const float* a1vW = (const float*)d_in[20]; const float* a1vb = (const float*)d_in[21];
    const float* a1g  = (const float*)d_in[22];
    const float* a2qW = (const float*)d_in[23]; const float* a2qb = (const float*)d_in[24];
    const float* a2kW = (const float*)d_in[25]; const float* a2kb = (const float*)d_in[26];
    const float* a2vW = (const float*)d_in[27]; const float* a2vb = (const float*)d_in[28];
    const float* a2g  = (const float*)d_in[29];

    float *a1p, *a2p, *a3p, *qp, *kp, *vp, *Ep, *t1p, *a4p, *t2p, *sig;
    cudaGetSymbolAddress((void**)&a1p, g_a1);
    cudaGetSymbolAddress((void**)&a2p, g_a2);
    cudaGetSymbolAddress((void**)&a3p, g_a3);
    cudaGetSymbolAddress((void**)&qp,  g_q);
    cudaGetSymbolAddress((void**)&kp,  g_kk);
    cudaGetSymbolAddress((void**)&vp,  g_v);
    cudaGetSymbolAddress((void**)&Ep,  g_E);
    cudaGetSymbolAddress((void**)&t1p, g_t1);
    cudaGetSymbolAddress((void**)&a4p, g_a4);
    cudaGetSymbolAddress((void**)&t2p, g_t2);
    cudaGetSymbolAddress((void**)&sig, g_sig);

    const int N = NPIX;
    const size_t NN = (size_t)N * N;

    // spectral norms -> 1/sigma scalars
    snorm_kernel<<<1, 256>>>(W1, u1, 64,  6,   sig + 0);
    snorm_kernel<<<1, 256>>>(W2, u2, 128, 64,  sig + 1);
    snorm_kernel<<<1, 256>>>(W3, u3, 256, 128, sig + 2);
    snorm_kernel<<<1, 256>>>(W4, u4, 512, 256, sig + 3);
    snorm_kernel<<<1, 256>>>(W5, u5, 1,   512, sig + 4);

    auto grid = [&](int M) { return dim3(N / BN, (M + BM - 1) / BM, BATCH); };

    // conv1/2/3 (SN + leaky)
    gemm_k<0,0,0><<<grid(64), 256>>>(W1, inp, a1p, 64, N, 6,   6,   N, N, 0, (size_t)6*N,   (size_t)64*N,  0, b1, sig+0, nullptr, nullptr);
    gemm_k<0,0,0><<<grid(128),256>>>(W2, a1p, a2p, 128, N, 64, 64,  N, N, 0, (size_t)64*N,  (size_t)128*N, 0, b2, sig+1, nullptr, nullptr);
    gemm_k<0,0,0><<<grid(256),256>>>(W3, a2p, a3p, 256, N, 128,128, N, N, 0, (size_t)128*N, (size_t)256*N, 0, b3, sig+2, nullptr, nullptr);

    // ---- attention 1 (C=256, Cq=32)
    gemm_k<0,0,1><<<grid(32), 256>>>(a1qW, a3p, qp, 32,  N, 256, 256, N, N, 0, (size_t)256*N, (size_t)32*N,  0, a1qb, nullptr, nullptr, nullptr);
    gemm_k<0,0,1><<<grid(32), 256>>>(a1kW, a3p, kp, 32,  N, 256, 256, N, N, 0, (size_t)256*N, (size_t)32*N,  0, a1kb, nullptr, nullptr, nullptr);
    gemm_k<0,0,1><<<grid(256),256>>>(a1vW, a3p, vp, 256, N, 256, 256, N, N, 0, (size_t)256*N, (size_t)256*N, 0, a1vb, nullptr, nullptr, nullptr);
    // energy[n,m] = sum_c q[c,n] k[c,m]
    gemm_k<1,0,2><<<dim3(N/BN, N/BM, BATCH), 256>>>(qp, kp, Ep, N, N, 32, N, N, N,
                                                    (size_t)32*N, (size_t)32*N, NN, 0,
                                                    nullptr, nullptr, nullptr, nullptr);
    softmax_rows<<<BATCH * N, 256>>>(Ep, N);
    // aw[c,m] = sum_n v[c,n] P[m,n]; out = gamma*aw + x
    gemm_k<0,1,3><<<grid(256), 256>>>(vp, Ep, t1p, 256, N, N, N, N, N,
                                      (size_t)256*N, NN, (size_t)256*N, (size_t)256*N,
                                      nullptr, nullptr, a1g, a3p);

    // conv4
    gemm_k<0,0,0><<<grid(512),256>>>(W4, t1p, a4p, 512, N, 256, 256, N, N, 0, (size_t)256*N, (size_t)512*N, 0, b4, sig+3, nullptr, nullptr);

    // ---- attention 2 (C=512, Cq=64)
    gemm_k<0,0,1><<<grid(64), 256>>>(a2qW, a4p, qp, 64,  N, 512, 512, N, N, 0, (size_t)512*N, (size_t)64*N,  0, a2qb, nullptr, nullptr, nullptr);
    gemm_k<0,0,1><<<grid(64), 256>>>(a2kW, a4p, kp, 64,  N, 512, 512, N, N, 0, (size_t)512*N, (size_t)64*N,  0, a2kb, nullptr, nullptr, nullptr);
    gemm_k<0,0,1><<<grid(512),256>>>(a2vW, a4p, vp, 512, N, 512, 512, N, N, 0, (size_t)512*N, (size_t)512*N, 0, a2vb, nullptr, nullptr, nullptr);
    gemm_k<1,0,2><<<dim3(N/BN, N/BM, BATCH), 256>>>(qp, kp, Ep, N, N, 64, N, N, N,
                                                    (size_t)64*N, (size_t)64*N, NN, 0,
                                                    nullptr, nullptr, nullptr, nullptr);
    softmax_rows<<<BATCH * N, 256>>>(Ep, N);
    gemm_k<0,1,3><<<grid(512), 256>>>(vp, Ep, t2p, 512, N, N, N, N, N,
                                      (size_t)512*N, NN, (size_t)512*N, (size_t)512*N,
                                      nullptr, nullptr, a2g, a4p);

    // conv5 (SN + leaky) -> output (B, H, W) = (4, 4096)
    gemm_k<0,0,0><<<grid(1), 256>>>(W5, t2p, (float*)d_out, 1, N, 512, 512, N, N,
                                    0, (size_t)512*N, (size_t)N, 0, b5, sig+4, nullptr, nullptr);
}

// round 4
// speedup vs baseline: 1.3046x; 1.3046x over previous
#include <cuda_runtime.h>
#include <cuda_bf16.h>
#include <math.h>
#include <stdint.h>

// ---------------------------------------------------------------------------
// SpectralDiscriminator on GB300 — tf32 mma.sync tensor-core GEMMs.
// B=4, N=64*64=4096. Every op is a GEMM over channels + softmax.
// ---------------------------------------------------------------------------

#define NPIX 4096
#define BATCH 4

__device__ float g_a1[BATCH * 64  * NPIX];                 //  4 MB
__device__ float g_a2[BATCH * 128 * NPIX];                 //  8 MB
__device__ float g_a3[BATCH * 256 * NPIX];                 // 16 MB
__device__ float g_q [BATCH * 64  * NPIX];                 //  4 MB (holds qT: [N][Cq])
__device__ float g_kk[BATCH * 64  * NPIX];                 //  4 MB
__device__ float g_v [BATCH * 512 * NPIX];                 // 32 MB
__device__ float g_E [(size_t)BATCH * NPIX * NPIX];        // 256 MB
__device__ float g_t1[BATCH * 256 * NPIX];                 // 16 MB
__device__ float g_a4[BATCH * 512 * NPIX];                 // 32 MB
__device__ float g_t2[BATCH * 512 * NPIX];                 // 32 MB
__device__ float g_sig[8];

// ---------------------------------------------------------------------------
// helpers
// ---------------------------------------------------------------------------
__device__ __forceinline__ float to_tf32(float x) {
    uint32_t u;
    asm("cvt.rna.tf32.f32 %0, %1;" : "=r"(u) : "f"(x));
    return __uint_as_float(u);
}

__device__ __forceinline__ void mma8(float* d, const uint32_t* a, uint32_t b0, uint32_t b1) {
    asm volatile(
        "mma.sync.aligned.m16n8k8.row.col.f32.tf32.tf32.f32 "
        "{%0,%1,%2,%3}, {%4,%5,%6,%7}, {%8,%9}, {%0,%1,%2,%3};"
        : "+f"(d[0]), "+f"(d[1]), "+f"(d[2]), "+f"(d[3])
        : "r"(a[0]), "r"(a[1]), "r"(a[2]), "r"(a[3]), "r"(b0), "r"(b1));
}

// swizzled flat index into a [128][32] float tile (rows = 128B = bank period)
__device__ __forceinline__ int swz(int r, int k) {
    return r * 32 + ((k & 3) | ((((k >> 2) ^ r) & 7) << 2));
}

// ---------------------------------------------------------------------------
// tile loaders: write into swizzled [128][32] smem tile
// ---------------------------------------------------------------------------
// rows have contiguous k (row-major along k). Used for A tiles and TB=1 B tiles.
__device__ __forceinline__ void ld_kcontig(float* dst, const float* src, int ld,
                                           int rmax, int K, int r0, int k0,
                                           int tid, bool fast) {
    #pragma unroll
    for (int i = 0; i < 4; i++) {
        int e = tid + i * 256;          // 0..1023
        int r = e >> 3, kq = e & 7;
        int gr = r0 + r;
        float4 v = make_float4(0.f, 0.f, 0.f, 0.f);
        if (gr < rmax) {
            const float* p = src + (size_t)gr * ld + k0 + kq * 4;
            if (fast) {
                v = *(const float4*)p;
            } else {
                int gk = k0 + kq * 4;
                if (gk     < K) v.x = p[0];
                if (gk + 1 < K) v.y = p[1];
                if (gk + 2 < K) v.z = p[2];
                if (gk + 3 < K) v.w = p[3];
            }
        }
        v.x = to_tf32(v.x); v.y = to_tf32(v.y);
        v.z = to_tf32(v.z); v.w = to_tf32(v.w);
        *(float4*)&dst[r * 32 + ((kq ^ (r & 7)) << 2)] = v;
    }
}

// B stored [K][N] with n contiguous (conv activations). Gather 4 k's per thread.
__device__ __forceinline__ void ld_ncontig(float* dst, const float* src, int ld,
                                           int K, int n0, int k0, int tid) {
    #pragma unroll
    for (int i = 0; i < 4; i++) {
        int e = tid + i * 256;
        int n = e & 127, kq = e >> 7;   // kq 0..7 across iterations
        int gn = n0 + n;                // N is always a multiple of 128
        int gk = k0 + kq * 4;
        const float* p = src + (size_t)gk * ld + gn;
        float4 v;
        v.x = (gk     < K) ? p[0]              : 0.f;
        v.y = (gk + 1 < K) ? p[ld]             : 0.f;
        v.z = (gk + 2 < K) ? p[2 * (size_t)ld] : 0.f;
        v.w = (gk + 3 < K) ? p[3 * (size_t)ld] : 0.f;
        v.x = to_tf32(v.x); v.y = to_tf32(v.y);
        v.z = to_tf32(v.z); v.w = to_tf32(v.w);
        *(float4*)&dst[n * 32 + ((kq ^ (n & 7)) << 2)] = v;
    }
}

// ---------------------------------------------------------------------------
// tf32 tensor-core GEMM: C[M,N] = sum_k A[m,k] B[k,n]
//   A always row-major (k contiguous), lda.
//   TBT=0: B[k,n] = B[k*ldb+n]   (n contiguous)
//   TBT=1: B[k,n] = B[n*ldb+k]   (k contiguous -- attention P operand)
// Epilogues:
//   EPI=0: leaky(scale*acc + bias[m], 0.1)
//   EPI=1: acc + bias[m]
//   EPI=2: acc
//   EPI=3: gamma*acc + Res[m*ldc+n]
//   EPI=4: acc + bias[m], stored TRANSPOSED: C[n*ldc + m]
// ---------------------------------------------------------------------------
template<int TBT, int EPI>
__global__ void __launch_bounds__(256, 2)
mma_gemm(const float* __restrict__ A, const float* __restrict__ B, float* __restrict__ Cm,
         int M, int N, int K, int lda, int ldb, int ldc,
         size_t sA, size_t sB, size_t sC, size_t sR,
         const float* __restrict__ bias, const float* __restrict__ scaleP,
         const float* __restrict__ gammaP, const float* __restrict__ Res)
{
    __shared__ float As[128 * 32];
    __shared__ float Bs[128 * 32];

    int bz = blockIdx.z;
    A  += sA * bz;
    B  += sB * bz;
    Cm += sC * bz;
    const float* R = (EPI == 3) ? (Res + sR * bz) : nullptr;

    int m0 = blockIdx.y * 128;
    int n0 = blockIdx.x * 128;
    int tid = threadIdx.x;
    int lane = tid & 31, wid = tid >> 5;
    int wm = (wid & 3) * 32;        // warp M offset within block tile
    int wn = (wid >> 2) * 64;       // warp N offset
    int g = lane >> 2, tig = lane & 3;

    bool fastA = ((K & 31) == 0) && ((lda & 3) == 0);
    bool fastB = ((K & 31) == 0) && ((ldb & 3) == 0);

    float acc[2][8][4];
    #pragma unroll
    for (int a = 0; a < 2; a++)
        #pragma unroll
        for (int b = 0; b < 8; b++)
            #pragma unroll
            for (int c = 0; c < 4; c++) acc[a][b][c] = 0.f;

    for (int k0 = 0; k0 < K; k0 += 32) {
        ld_kcontig(As, A, lda, M, K, m0, k0, tid, fastA);
        if (TBT == 0) ld_ncontig(Bs, B, ldb, K, n0, k0, tid);
        else          ld_kcontig(Bs, B, ldb, N, K, n0, k0, tid, fastB);
        __syncthreads();

        #pragma unroll
        for (int ks = 0; ks < 4; ks++) {
            int kb = ks * 8 + tig;
            uint32_t afr[2][4];
            #pragma unroll
            for (int mt = 0; mt < 2; mt++) {
                int r = wm + mt * 16 + g;
                afr[mt][0] = __float_as_uint(As[swz(r,     kb)]);
                afr[mt][1] = __float_as_uint(As[swz(r + 8, kb)]);
                afr[mt][2] = __float_as_uint(As[swz(r,     kb + 4)]);
                afr[mt][3] = __float_as_uint(As[swz(r + 8, kb + 4)]);
            }
            #pragma unroll
            for (int nt = 0; nt < 8; nt++) {
                int n = wn + nt * 8 + g;
                uint32_t b0 = __float_as_uint(Bs[swz(n, kb)]);
                uint32_t b1 = __float_as_uint(Bs[swz(n, kb + 4)]);
                mma8(acc[0][nt], afr[0], b0, b1);
                mma8(acc[1][nt], afr[1], b0, b1);
            }
        }
        __syncthreads();
    }

    float scl = (EPI == 0) ? *scaleP : 1.f;
    float gam = (EPI == 3) ? *gammaP : 0.f;

    #pragma unroll
    for (int mt = 0; mt < 2; mt++) {
        #pragma unroll
        for (int half = 0; half < 2; half++) {
            int gm = m0 + wm + mt * 16 + g + half * 8;
            if (gm >= M) continue;
            float bv = (EPI == 0 || EPI == 1 || EPI == 4) ? bias[gm] : 0.f;
            #pragma unroll
            for (int nt = 0; nt < 8; nt++) {
                int gn = n0 + wn + nt * 8 + tig * 2;
                float v0 = acc[mt][nt][half * 2 + 0];
                float v1 = acc[mt][nt][half * 2 + 1];
                if (EPI == 0) {
                    v0 = v0 * scl + bv; v0 = (v0 > 0.f) ? v0 : 0.1f * v0;
                    v1 = v1 * scl + bv; v1 = (v1 > 0.f) ? v1 : 0.1f * v1;
                } else if (EPI == 1 || EPI == 4) {
                    v0 += bv; v1 += bv;
                } else if (EPI == 3) {
                    const float* rp = R + (size_t)gm * ldc + gn;
                    v0 = gam * v0 + rp[0];
                    v1 = gam * v1 + rp[1];
                }
                if (EPI == 4) {
                    Cm[(size_t)gn * ldc + gm]       = v0;
                    Cm[(size_t)(gn + 1) * ldc + gm] = v1;
                } else {
                    *(float2*)&Cm[(size_t)gm * ldc + gn] = make_float2(v0, v1);
                }
            }
        }
    }
}

// ---------------------------------------------------------------------------
// All 5 spectral norms in one kernel (one block per layer, warp-parallel).
// sigma = ||W v||  with  v = normalize(W^T u);  writes 1/sigma.
// ---------------------------------------------------------------------------
__global__ void snorm_all(const float* __restrict__ W1, const float* __restrict__ u1,
                          const float* __restrict__ W2, const float* __restrict__ u2,
                          const float* __restrict__ W3, const float* __restrict__ u3,
                          const float* __restrict__ W4, const float* __restrict__ u4,
                          const float* __restrict__ W5, const float* __restrict__ u5,
                          float* __restrict__ sig)
{
    __shared__ float vs[512];
    __shared__ float us[512];
    __shared__ float red[256];
    __shared__ float red8[8];

    const float* W; const float* u; int O, C;
    switch (blockIdx.x) {
        case 0: W = W1; u = u1; O = 64;  C = 6;   break;
        case 1: W = W2; u = u2; O = 128; C = 64;  break;
        case 2: W = W3; u = u3; O = 256; C = 128; break;
        case 3: W = W4; u = u4; O = 512; C = 256; break;
        default: W = W5; u = u5; O = 1;  C = 512; break;
    }

    int t = threadIdx.x, lane = t & 31, wid = t >> 5;

    for (int o = t; o < O; o += 256) us[o] = u[o];
    __syncthreads();

    // v[c] = sum_o W[o,c] u[o]
    for (int c = t; c < C; c += 256) {
        float s = 0.f;
        #pragma unroll 4
        for (int o = 0; o < O; o++) s += W[(size_t)o * C + c] * us[o];
        vs[c] = s;
    }
    __syncthreads();

    float s = 0.f;
    for (int c = t; c < C; c += 256) s += vs[c] * vs[c];
    red[t] = s; __syncthreads();
    for (int off = 128; off > 0; off >>= 1) { if (t < off) red[t] += red[t + off]; __syncthreads(); }
    float vinv = 1.f / (sqrtf(red[0]) + 1e-12f);
    __syncthreads();
    for (int c = t; c < C; c += 256) vs[c] *= vinv;
    __syncthreads();

    // ||W v||^2, warp per output row
    float accq = 0.f;
    for (int o = wid; o < O; o += 8) {
        float tv = 0.f;
        for (int c = lane; c < C; c += 32) tv += W[(size_t)o * C + c] * vs[c];
        #pragma unroll
        for (int off = 16; off > 0; off >>= 1) tv += __shfl_xor_sync(0xffffffffu, tv, off);
        if (lane == 0) accq += tv * tv;
    }
    if (lane == 0) red8[wid] = accq;
    __syncthreads();
    if (t == 0) {
        float S = 0.f;
        #pragma unroll
        for (int w = 0; w < 8; w++) S += red8[w];
        float sigma = S / (sqrtf(S) + 1e-12f);
        sig[blockIdx.x] = 1.f / sigma;
    }
}

// ---------------------------------------------------------------------------
// Online 2-pass row softmax (row length 4096), float4, one block per row.
// ---------------------------------------------------------------------------
__global__ void softmax_rows(float* __restrict__ E) {
    __shared__ float rm[256], rs[256];
    float4* r4 = (float4*)(E + (size_t)blockIdx.x * NPIX);
    int t = threadIdx.x;

    float mx = -3.0e38f, sm = 0.f;
    for (int i = t; i < NPIX / 4; i += 256) {
        float4 v = r4[i];
        float m4 = fmaxf(fmaxf(v.x, v.y), fmaxf(v.z, v.w));
        if (m4 > mx) { sm *= __expf(mx - m4); mx = m4; }
        sm += __expf(v.x - mx) + __expf(v.y - mx) + __expf(v.z - mx) + __expf(v.w - mx);
    }
    rm[t] = mx; rs[t] = sm; __syncthreads();
    for (int off = 128; off > 0; off >>= 1) {
        if (t < off) {
            float m1 = rm[t], m2 = rm[t + off];
            float M = fmaxf(m1, m2);
            rs[t] = rs[t] * __expf(m1 - M) + rs[t + off] * __expf(m2 - M);
            rm[t] = M;
        }
        __syncthreads();
    }
    float M = rm[0];
    float inv = 1.f / rs[0];

    for (int i = t; i < NPIX / 4; i += 256) {
        float4 v = r4[i];
        v.x = __expf(v.x - M) * inv;
        v.y = __expf(v.y - M) * inv;
        v.z = __expf(v.z - M) * inv;
        v.w = __expf(v.w - M) * inv;
        r4[i] = v;
    }
}

// ---------------------------------------------------------------------------
// kernel_launch
// ---------------------------------------------------------------------------
extern "C" void kernel_launch(void* const* d_in, const int* in_sizes, int n_in,
                              void* d_out, int out_size)
{
    const float* inp  = (const float*)d_in[0];
    const float* W1 = (const float*)d_in[1];  const float* b1 = (const float*)d_in[2];  const float* u1 = (const float*)d_in[3];
    const float* W2 = (const float*)d_in[4];  const float* b2 = (const float*)d_in[5];  const float* u2 = (const float*)d_in[6];
    const float* W3 = (const float*)d_in[7];  const float* b3 = (const float*)d_in[8];  const float* u3 = (const float*)d_in[9];
    const float* W4 = (const float*)d_in[10]; const float* b4 = (const float*)d_in[11]; const float* u4 = (const float*)d_in[12];
    const float* W5 = (const float*)d_in[13]; const float* b5 = (const float*)d_in[14]; const float* u5 = (const float*)d_in[15];
    const float* a1qW = (const float*)d_in[16]; const float* a1qb = (const float*)d_in[17];
    const float* a1kW = (const float*)d_in[18]; const float* a1kb = (const float*)d_in[19];
    const float* a1vW = (const float*)d_in[20]; const float* a1vb = (const float*)d_in[21];
    const float* a1g  = (const float*)d_in[22];
    const float* a2qW = (const float*)d_in[23]; const float* a2qb = (const float*)d_in[24];
    const float* a2kW = (const float*)d_in[25]; const float* a2kb = (const float*)d_in[26];
    const float* a2vW = (const float*)d_in[27]; const float* a2vb = (const float*)d_in[28];
    const float* a2g  = (const float*)d_in[29];

    float *a1p, *a2p, *a3p, *qp, *kp, *vp, *Ep, *t1p, *a4p, *t2p, *sig;
    cudaGetSymbolAddress((void**)&a1p, g_a1);
    cudaGetSymbolAddress((void**)&a2p, g_a2);
    cudaGetSymbolAddress((void**)&a3p, g_a3);
    cudaGetSymbolAddress((void**)&qp,  g_q);
    cudaGetSymbolAddress((void**)&kp,  g_kk);
    cudaGetSymbolAddress((void**)&vp,  g_v);
    cudaGetSymbolAddress((void**)&Ep,  g_E);
    cudaGetSymbolAddress((void**)&t1p, g_t1);
    cudaGetSymbolAddress((void**)&a4p, g_a4);
    cudaGetSymbolAddress((void**)&t2p, g_t2);
    cudaGetSymbolAddress((void**)&sig, g_sig);

    const int N = NPIX;
    const size_t NN = (size_t)N * N;

    snorm_all<<<5, 256>>>(W1, u1, W2, u2, W3, u3, W4, u4, W5, u5, sig);

    auto grid = [&](int M) { return dim3(N / 128, (M + 127) / 128, BATCH); };

    // conv1/2/3 (SN + leaky)
    mma_gemm<0,0><<<grid(64), 256>>>(W1, inp, a1p, 64, N, 6, 6, N, N,
        0, (size_t)6*N, (size_t)64*N, 0, b1, sig+0, nullptr, nullptr);
    mma_gemm<0,0><<<grid(128),256>>>(W2, a1p, a2p, 128, N, 64, 64, N, N,
        0, (size_t)64*N, (size_t)128*N, 0, b2, sig+1, nullptr, nullptr);
    mma_gemm<0,0><<<grid(256),256>>>(W3, a2p, a3p, 256, N, 128, 128, N, N,
        0, (size_t)128*N, (size_t)256*N, 0, b3, sig+2, nullptr, nullptr);

    // ---- attention 1 (C=256, Cq=32)
    // q stored transposed: qT[N][32]
    mma_gemm<0,4><<<grid(32), 256>>>(a1qW, a3p, qp, 32, N, 256, 256, N, 32,
        0, (size_t)256*N, (size_t)32*N, 0, a1qb, nullptr, nullptr, nullptr);
    mma_gemm<0,1><<<grid(32), 256>>>(a1kW, a3p, kp, 32, N, 256, 256, N, N,
        0, (size_t)256*N, (size_t)32*N, 0, a1kb, nullptr, nullptr, nullptr);
    mma_gemm<0,1><<<grid(256),256>>>(a1vW, a3p, vp, 256, N, 256, 256, N, N,
        0, (size_t)256*N, (size_t)256*N, 0, a1vb, nullptr, nullptr, nullptr);
    // E[n,m] = sum_c qT[n,c] k[c,m]
    mma_gemm<0,2><<<dim3(N/128, N/128, BATCH), 256>>>(qp, kp, Ep, N, N, 32, 32, N, N,
        (size_t)32*N, (size_t)32*N, NN, 0, nullptr, nullptr, nullptr, nullptr);
    softmax_rows<<<BATCH * N, 256>>>(Ep);
    // aw[c,m] = sum_n v[c,n] P[m,n];  t1 = gamma*aw + a3
    mma_gemm<1,3><<<grid(256), 256>>>(vp, Ep, t1p, 256, N, N, N, N, N,
        (size_t)256*N, NN, (size_t)256*N, (size_t)256*N, nullptr, nullptr, a1g, a3p);

    // conv4
    mma_gemm<0,0><<<grid(512),256>>>(W4, t1p, a4p, 512, N, 256, 256, N, N,
        0, (size_t)256*N, (size_t)512*N, 0, b4, sig+3, nullptr, nullptr);

    // ---- attention 2 (C=512, Cq=64)
    mma_gemm<0,4><<<grid(64), 256>>>(a2qW, a4p, qp, 64, N, 512, 512, N, 64,
        0, (size_t)512*N, (size_t)64*N, 0, a2qb, nullptr, nullptr, nullptr);
    mma_gemm<0,1><<<grid(64), 256>>>(a2kW, a4p, kp, 64, N, 512, 512, N, N,
        0, (size_t)512*N, (size_t)64*N, 0, a2kb, nullptr, nullptr, nullptr);
    mma_gemm<0,1><<<grid(512),256>>>(a2vW, a4p, vp, 512, N, 512, 512, N, N,
        0, (size_t)512*N, (size_t)512*N, 0, a2vb, nullptr, nullptr, nullptr);
    mma_gemm<0,2><<<dim3(N/128, N/128, BATCH), 256>>>(qp, kp, Ep, N, N, 64, 64, N, N,
        (size_t)64*N, (size_t)64*N, NN, 0, nullptr, nullptr, nullptr, nullptr);
    softmax_rows<<<BATCH * N, 256>>>(Ep);
    mma_gemm<1,3><<<grid(512), 256>>>(vp, Ep, t2p, 512, N, N, N, N, N,
        (size_t)512*N, NN, (size_t)512*N, (size_t)512*N, nullptr, nullptr, a2g, a4p);

    // conv5 -> (B, H, W)
    mma_gemm<0,0><<<grid(1), 256>>>(W5, t2p, (float*)d_out, 1, N, 512, 512, N, N,
        0, (size_t)512*N, (size_t)N, 0, b5, sig+4, nullptr, nullptr);
}

// round 5
// speedup vs baseline: 2.1223x; 1.6268x over previous
#include <cuda_runtime.h>
#include <cuda_bf16.h>
#include <math.h>
#include <stdint.h>

// ---------------------------------------------------------------------------
// SpectralDiscriminator on GB300 — tf32 mma.sync, LDS.64 fragment path,
// software-pipelined global loads.  B=4, N=4096.
// ---------------------------------------------------------------------------

#define NPIX 4096
#define BATCH 4

__device__ float g_a1[BATCH * 64  * NPIX];
__device__ float g_a2[BATCH * 128 * NPIX];
__device__ float g_a3[BATCH * 256 * NPIX];
__device__ float g_q [BATCH * 64  * NPIX];        // qT: [N][Cq]
__device__ float g_kk[BATCH * 64  * NPIX];
__device__ float g_v [BATCH * 512 * NPIX];
__device__ float g_E [(size_t)BATCH * NPIX * NPIX];
__device__ float g_t1[BATCH * 256 * NPIX];
__device__ float g_a4[BATCH * 512 * NPIX];
__device__ float g_t2[BATCH * 512 * NPIX];
__device__ float g_sig[8];

__device__ __forceinline__ void mma8(float* d, const uint32_t* a, uint32_t b0, uint32_t b1) {
    asm volatile(
        "mma.sync.aligned.m16n8k8.row.col.f32.tf32.tf32.f32 "
        "{%0,%1,%2,%3}, {%4,%5,%6,%7}, {%8,%9}, {%0,%1,%2,%3};"
        : "+f"(d[0]), "+f"(d[1]), "+f"(d[2]), "+f"(d[3])
        : "r"(a[0]), "r"(a[1]), "r"(a[2]), "r"(a[3]), "r"(b0), "r"(b1));
}

// ---------------------------------------------------------------------------
// gmem -> regs loaders (128x32 tile, 4 float4 per thread)
// ---------------------------------------------------------------------------
__device__ __forceinline__ void ldg_kcontig(float4* rv, const float* src, int ld,
                                            int rmax, int K, int r0, int k0,
                                            int tid, bool fast) {
    #pragma unroll
    for (int i = 0; i < 4; i++) {
        int e = tid + i * 256;
        int r = e >> 3, kq = e & 7;
        int gr = r0 + r;
        float4 v = make_float4(0.f, 0.f, 0.f, 0.f);
        if (gr < rmax) {
            const float* p = src + (size_t)gr * ld + k0 + kq * 4;
            if (fast) {
                v = *(const float4*)p;
            } else {
                int gk = k0 + kq * 4;
                if (gk     < K) v.x = p[0];
                if (gk + 1 < K) v.y = p[1];
                if (gk + 2 < K) v.z = p[2];
                if (gk + 3 < K) v.w = p[3];
            }
        }
        rv[i] = v;
    }
}

__device__ __forceinline__ void ldg_ncontig(float4* rv, const float* src, int ld,
                                            int K, int n0, int k0, int tid) {
    #pragma unroll
    for (int i = 0; i < 4; i++) {
        int e = tid + i * 256;
        int n = e & 127, kq = e >> 7;
        int gk = k0 + kq * 4;
        const float* p = src + (size_t)gk * ld + n0 + n;
        float4 v = make_float4(0.f, 0.f, 0.f, 0.f);
        if (gk     < K) v.x = p[0];
        if (gk + 1 < K) v.y = p[(size_t)ld];
        if (gk + 2 < K) v.z = p[2 * (size_t)ld];
        if (gk + 3 < K) v.w = p[3 * (size_t)ld];
        rv[i] = v;
    }
}

// ---------------------------------------------------------------------------
// regs -> smem stores into k-interleaved swizzled layout:
//   word(r,k) = r*32 + (((s ^ (r&7)) << 1) | h),  s=(k&3)*4+(k>>3), h=(k>>2)&1
// thread's float4 covers k = 4*kq .. 4*kq+3  ->  s = j*4 + (kq>>1), h = kq&1
// ---------------------------------------------------------------------------
__device__ __forceinline__ void sts_kcontig(float* dst, const float4* rv, int tid) {
    #pragma unroll
    for (int i = 0; i < 4; i++) {
        int e = tid + i * 256;
        int r = e >> 3, kq = e & 7;
        int b = kq >> 1, h = kq & 1, rs = r & 7;
        float vv[4] = {rv[i].x, rv[i].y, rv[i].z, rv[i].w};
        #pragma unroll
        for (int j = 0; j < 4; j++)
            dst[r * 32 + ((((j * 4 + b) ^ rs) << 1) | h)] = vv[j];
    }
}

__device__ __forceinline__ void sts_ncontig(float* dst, const float4* rv, int tid) {
    #pragma unroll
    for (int i = 0; i < 4; i++) {
        int e = tid + i * 256;
        int n = e & 127, kq = e >> 7;
        int b = kq >> 1, h = kq & 1, rs = n & 7;
        float vv[4] = {rv[i].x, rv[i].y, rv[i].z, rv[i].w};
        #pragma unroll
        for (int j = 0; j < 4; j++)
            dst[n * 32 + ((((j * 4 + b) ^ rs) << 1) | h)] = vv[j];
    }
}

// ---------------------------------------------------------------------------
// tf32 tensor-core GEMM: C[M,N] = sum_k A[m,k] B[k,n]
//   A row-major (k contiguous).  TBT=0: B[k*ldb+n];  TBT=1: B[n*ldb+k]
// EPI: 0 leaky(scale*acc+bias)  1 acc+bias  2 acc  3 gamma*acc+Res  4 acc+bias, C transposed
// ---------------------------------------------------------------------------
template<int TBT, int EPI>
__global__ void __launch_bounds__(256, 2)
mma_gemm(const float* __restrict__ A, const float* __restrict__ B, float* __restrict__ Cm,
         int M, int N, int K, int lda, int ldb, int ldc,
         size_t sA, size_t sB, size_t sC, size_t sR,
         const float* __restrict__ bias, const float* __restrict__ scaleP,
         const float* __restrict__ gammaP, const float* __restrict__ Res)
{
    __shared__ float As[128 * 32];
    __shared__ float Bs[128 * 32];

    int bz = blockIdx.z;
    A  += sA * bz;
    B  += sB * bz;
    Cm += sC * bz;
    const float* R = (EPI == 3) ? (Res + sR * bz) : nullptr;

    int m0 = blockIdx.y * 128;
    int n0 = blockIdx.x * 128;
    int tid = threadIdx.x;
    int lane = tid & 31, wid = tid >> 5;
    int wm = (wid & 3) * 32;
    int wn = (wid >> 2) * 64;
    int g = lane >> 2, tig = lane & 3;

    bool fastA = ((K & 31) == 0) && ((lda & 3) == 0);
    bool fastB = ((K & 31) == 0) && ((ldb & 3) == 0);

    float acc[2][8][4];
    #pragma unroll
    for (int a = 0; a < 2; a++)
        #pragma unroll
        for (int b = 0; b < 8; b++)
            #pragma unroll
            for (int c = 0; c < 4; c++) acc[a][b][c] = 0.f;

    float4 ra[4], rb[4];
    ldg_kcontig(ra, A, lda, M, K, m0, 0, tid, fastA);
    if (TBT == 0) ldg_ncontig(rb, B, ldb, K, n0, 0, tid);
    else          ldg_kcontig(rb, B, ldb, N, K, n0, 0, tid, fastB);

    int nk = (K + 31) >> 5;
    for (int kt = 0; kt < nk; kt++) {
        sts_kcontig(As, ra, tid);
        if (TBT == 0) sts_ncontig(Bs, rb, tid);
        else          sts_kcontig(Bs, rb, tid);
        __syncthreads();

        if (kt + 1 < nk) {
            int k0 = (kt + 1) * 32;
            ldg_kcontig(ra, A, lda, M, K, m0, k0, tid, fastA);
            if (TBT == 0) ldg_ncontig(rb, B, ldb, K, n0, k0, tid);
            else          ldg_kcontig(rb, B, ldb, N, K, n0, k0, tid, fastB);
        }

        #pragma unroll
        for (int ks = 0; ks < 4; ks++) {
            int swz = ((tig * 4 + ks) ^ g) << 1;
            uint32_t afr[2][4];
            #pragma unroll
            for (int mt = 0; mt < 2; mt++) {
                int r0 = wm + mt * 16 + g;
                float2 p0 = *(const float2*)&As[r0 * 32 + swz];
                float2 p1 = *(const float2*)&As[(r0 + 8) * 32 + swz];
                afr[mt][0] = __float_as_uint(p0.x);
                afr[mt][1] = __float_as_uint(p1.x);
                afr[mt][2] = __float_as_uint(p0.y);
                afr[mt][3] = __float_as_uint(p1.y);
            }
            #pragma unroll
            for (int nt = 0; nt < 8; nt++) {
                int n = wn + nt * 8 + g;
                float2 pb = *(const float2*)&Bs[n * 32 + swz];
                uint32_t b0 = __float_as_uint(pb.x);
                uint32_t b1 = __float_as_uint(pb.y);
                mma8(acc[0][nt], afr[0], b0, b1);
                mma8(acc[1][nt], afr[1], b0, b1);
            }
        }
        __syncthreads();
    }

    float scl = (EPI == 0) ? *scaleP : 1.f;
    float gam = (EPI == 3) ? *gammaP : 0.f;

    #pragma unroll
    for (int mt = 0; mt < 2; mt++) {
        #pragma unroll
        for (int half = 0; half < 2; half++) {
            int gm = m0 + wm + mt * 16 + g + half * 8;
            if (gm >= M) continue;
            float bv = (EPI == 0 || EPI == 1 || EPI == 4) ? bias[gm] : 0.f;
            #pragma unroll
            for (int nt = 0; nt < 8; nt++) {
                int gn = n0 + wn + nt * 8 + tig * 2;
                float v0 = acc[mt][nt][half * 2 + 0];
                float v1 = acc[mt][nt][half * 2 + 1];
                if (EPI == 0) {
                    v0 = v0 * scl + bv; v0 = (v0 > 0.f) ? v0 : 0.1f * v0;
                    v1 = v1 * scl + bv; v1 = (v1 > 0.f) ? v1 : 0.1f * v1;
                } else if (EPI == 1 || EPI == 4) {
                    v0 += bv; v1 += bv;
                } else if (EPI == 3) {
                    const float* rp = R + (size_t)gm * ldc + gn;
                    v0 = gam * v0 + rp[0];
                    v1 = gam * v1 + rp[1];
                }
                if (EPI == 4) {
                    Cm[(size_t)gn * ldc + gm]       = v0;
                    Cm[(size_t)(gn + 1) * ldc + gm] = v1;
                } else {
                    *(float2*)&Cm[(size_t)gm * ldc + gn] = make_float2(v0, v1);
                }
            }
        }
    }
}

// ---------------------------------------------------------------------------
// All 5 spectral norms, one block per layer.
// ---------------------------------------------------------------------------
__global__ void snorm_all(const float* __restrict__ W1, const float* __restrict__ u1,
                          const float* __restrict__ W2, const float* __restrict__ u2,
                          const float* __restrict__ W3, const float* __restrict__ u3,
                          const float* __restrict__ W4, const float* __restrict__ u4,
                          const float* __restrict__ W5, const float* __restrict__ u5,
                          float* __restrict__ sig)
{
    __shared__ float vs[512];
    __shared__ float us[512];
    __shared__ float red[256];
    __shared__ float red8[8];

    const float* W; const float* u; int O, C;
    switch (blockIdx.x) {
        case 0: W = W1; u = u1; O = 64;  C = 6;   break;
        case 1: W = W2; u = u2; O = 128; C = 64;  break;
        case 2: W = W3; u = u3; O = 256; C = 128; break;
        case 3: W = W4; u = u4; O = 512; C = 256; break;
        default: W = W5; u = u5; O = 1;  C = 512; break;
    }

    int t = threadIdx.x, lane = t & 31, wid = t >> 5;

    for (int o = t; o < O; o += 256) us[o] = u[o];
    __syncthreads();

    for (int c = t; c < C; c += 256) {
        float s = 0.f;
        #pragma unroll 4
        for (int o = 0; o < O; o++) s += W[(size_t)o * C + c] * us[o];
        vs[c] = s;
    }
    __syncthreads();

    float s = 0.f;
    for (int c = t; c < C; c += 256) s += vs[c] * vs[c];
    red[t] = s; __syncthreads();
    for (int off = 128; off > 0; off >>= 1) { if (t < off) red[t] += red[t + off]; __syncthreads(); }
    float vinv = 1.f / (sqrtf(red[0]) + 1e-12f);
    __syncthreads();
    for (int c = t; c < C; c += 256) vs[c] *= vinv;
    __syncthreads();

    float accq = 0.f;
    for (int o = wid; o < O; o += 8) {
        float tv = 0.f;
        for (int c = lane; c < C; c += 32) tv += W[(size_t)o * C + c] * vs[c];
        #pragma unroll
        for (int off = 16; off > 0; off >>= 1) tv += __shfl_xor_sync(0xffffffffu, tv, off);
        if (lane == 0) accq += tv * tv;
    }
    if (lane == 0) red8[wid] = accq;
    __syncthreads();
    if (t == 0) {
        float S = 0.f;
        #pragma unroll
        for (int w = 0; w < 8; w++) S += red8[w];
        float sigma = S / (sqrtf(S) + 1e-12f);
        sig[blockIdx.x] = 1.f / sigma;
    }
}

// ---------------------------------------------------------------------------
// Online 2-pass row softmax (row length 4096), one block per row.
// ---------------------------------------------------------------------------
__global__ void softmax_rows(float* __restrict__ E) {
    __shared__ float rm[256], rs[256];
    float4* r4 = (float4*)(E + (size_t)blockIdx.x * NPIX);
    int t = threadIdx.x;

    float mx = -3.0e38f, sm = 0.f;
    for (int i = t; i < NPIX / 4; i += 256) {
        float4 v = r4[i];
        float m4 = fmaxf(fmaxf(v.x, v.y), fmaxf(v.z, v.w));
        if (m4 > mx) { sm *= __expf(mx - m4); mx = m4; }
        sm += __expf(v.x - mx) + __expf(v.y - mx) + __expf(v.z - mx) + __expf(v.w - mx);
    }
    rm[t] = mx; rs[t] = sm; __syncthreads();
    for (int off = 128; off > 0; off >>= 1) {
        if (t < off) {
            float m1 = rm[t], m2 = rm[t + off];
            float M = fmaxf(m1, m2);
            rs[t] = rs[t] * __expf(m1 - M) + rs[t + off] * __expf(m2 - M);
            rm[t] = M;
        }
        __syncthreads();
    }
    float M = rm[0];
    float inv = 1.f / rs[0];

    for (int i = t; i < NPIX / 4; i += 256) {
        float4 v = r4[i];
        v.x = __expf(v.x - M) * inv;
        v.y = __expf(v.y - M) * inv;
        v.z = __expf(v.z - M) * inv;
        v.w = __expf(v.w - M) * inv;
        r4[i] = v;
    }
}

// ---------------------------------------------------------------------------
// kernel_launch
// ---------------------------------------------------------------------------
extern "C" void kernel_launch(void* const* d_in, const int* in_sizes, int n_in,
                              void* d_out, int out_size)
{
    const float* inp  = (const float*)d_in[0];
    const float* W1 = (const float*)d_in[1];  const float* b1 = (const float*)d_in[2];  const float* u1 = (const float*)d_in[3];
    const float* W2 = (const float*)d_in[4];  const float* b2 = (const float*)d_in[5];  const float* u2 = (const float*)d_in[6];
    const float* W3 = (const float*)d_in[7];  const float* b3 = (const float*)d_in[8];  const float* u3 = (const float*)d_in[9];
    const float* W4 = (const float*)d_in[10]; const float* b4 = (const float*)d_in[11]; const float* u4 = (const float*)d_in[12];
    const float* W5 = (const float*)d_in[13]; const float* b5 = (const float*)d_in[14]; const float* u5 = (const float*)d_in[15];
    const float* a1qW = (const float*)d_in[16]; const float* a1qb = (const float*)d_in[17];
    const float* a1kW = (const float*)d_in[18]; const float* a1kb = (const float*)d_in[19];
    const float* a1vW = (const float*)d_in[20]; const float* a1vb = (const float*)d_in[21];
    const float* a1g  = (const float*)d_in[22];
    const float* a2qW = (const float*)d_in[23]; const float* a2qb = (const float*)d_in[24];
    const float* a2kW = (const float*)d_in[25]; const float* a2kb = (const float*)d_in[26];
    const float* a2vW = (const float*)d_in[27]; const float* a2vb = (const float*)d_in[28];
    const float* a2g  = (const float*)d_in[29];

    float *a1p, *a2p, *a3p, *qp, *kp, *vp, *Ep, *t1p, *a4p, *t2p, *sig;
    cudaGetSymbolAddress((void**)&a1p, g_a1);
    cudaGetSymbolAddress((void**)&a2p, g_a2);
    cudaGetSymbolAddress((void**)&a3p, g_a3);
    cudaGetSymbolAddress((void**)&qp,  g_q);
    cudaGetSymbolAddress((void**)&kp,  g_kk);
    cudaGetSymbolAddress((void**)&vp,  g_v);
    cudaGetSymbolAddress((void**)&Ep,  g_E);
    cudaGetSymbolAddress((void**)&t1p, g_t1);
    cudaGetSymbolAddress((void**)&a4p, g_a4);
    cudaGetSymbolAddress((void**)&t2p, g_t2);
    cudaGetSymbolAddress((void**)&sig, g_sig);

    const int N = NPIX;
    const size_t NN = (size_t)N * N;

    snorm_all<<<5, 256>>>(W1, u1, W2, u2, W3, u3, W4, u4, W5, u5, sig);

    auto grid = [&](int M) { return dim3(N / 128, (M + 127) / 128, BATCH); };

    // conv1/2/3
    mma_gemm<0,0><<<grid(64), 256>>>(W1, inp, a1p, 64, N, 6, 6, N, N,
        0, (size_t)6*N, (size_t)64*N, 0, b1, sig+0, nullptr, nullptr);
    mma_gemm<0,0><<<grid(128),256>>>(W2, a1p, a2p, 128, N, 64, 64, N, N,
        0, (size_t)64*N, (size_t)128*N, 0, b2, sig+1, nullptr, nullptr);
    mma_gemm<0,0><<<grid(256),256>>>(W3, a2p, a3p, 256, N, 128, 128, N, N,
        0, (size_t)128*N, (size_t)256*N, 0, b3, sig+2, nullptr, nullptr);

    // ---- attention 1 (C=256, Cq=32)
    mma_gemm<0,4><<<grid(32), 256>>>(a1qW, a3p, qp, 32, N, 256, 256, N, 32,
        0, (size_t)256*N, (size_t)32*N, 0, a1qb, nullptr, nullptr, nullptr);
    mma_gemm<0,1><<<grid(32), 256>>>(a1kW, a3p, kp, 32, N, 256, 256, N, N,
        0, (size_t)256*N, (size_t)32*N, 0, a1kb, nullptr, nullptr, nullptr);
    mma_gemm<0,1><<<grid(256),256>>>(a1vW, a3p, vp, 256, N, 256, 256, N, N,
        0, (size_t)256*N, (size_t)256*N, 0, a1vb, nullptr, nullptr, nullptr);
    mma_gemm<0,2><<<dim3(N/128, N/128, BATCH), 256>>>(qp, kp, Ep, N, N, 32, 32, N, N,
        (size_t)32*N, (size_t)32*N, NN, 0, nullptr, nullptr, nullptr, nullptr);
    softmax_rows<<<BATCH * N, 256>>>(Ep);
    mma_gemm<1,3><<<grid(256), 256>>>(vp, Ep, t1p, 256, N, N, N, N, N,
        (size_t)256*N, NN, (size_t)256*N, (size_t)256*N, nullptr, nullptr, a1g, a3p);

    // conv4
    mma_gemm<0,0><<<grid(512),256>>>(W4, t1p, a4p, 512, N, 256, 256, N, N,
        0, (size_t)256*N, (size_t)512*N, 0, b4, sig+3, nullptr, nullptr);

    // ---- attention 2 (C=512, Cq=64)
    mma_gemm<0,4><<<grid(64), 256>>>(a2qW, a4p, qp, 64, N, 512, 512, N, 64,
        0, (size_t)512*N, (size_t)64*N, 0, a2qb, nullptr, nullptr, nullptr);
    mma_gemm<0,1><<<grid(64), 256>>>(a2kW, a4p, kp, 64, N, 512, 512, N, N,
        0, (size_t)512*N, (size_t)64*N, 0, a2kb, nullptr, nullptr, nullptr);
    mma_gemm<0,1><<<grid(512),256>>>(a2vW, a4p, vp, 512, N, 512, 512, N, N,
        0, (size_t)512*N, (size_t)512*N, 0, a2vb, nullptr, nullptr, nullptr);
    mma_gemm<0,2><<<dim3(N/128, N/128, BATCH), 256>>>(qp, kp, Ep, N, N, 64, 64, N, N,
        (size_t)64*N, (size_t)64*N, NN, 0, nullptr, nullptr, nullptr, nullptr);
    softmax_rows<<<BATCH * N, 256>>>(Ep);
    mma_gemm<1,3><<<grid(512), 256>>>(vp, Ep, t2p, 512, N, N, N, N, N,
        (size_t)512*N, NN, (size_t)512*N, (size_t)512*N, nullptr, nullptr, a2g, a4p);

    // conv5 -> (B, H, W)
    mma_gemm<0,0><<<grid(1), 256>>>(W5, t2p, (float*)d_out, 1, N, 512, 512, N, N,
        0, (size_t)512*N, (size_t)N, 0, b5, sig+4, nullptr, nullptr);
}

// round 7
// speedup vs baseline: 5.5513x; 2.6157x over previous
#include <cuda_runtime.h>
#include <cuda_fp16.h>
#include <math.h>
#include <stdint.h>

// ---------------------------------------------------------------------------
// SpectralDiscriminator on GB300 — fp16 mma.sync (m16n8k16) + cp.async +
// ldmatrix. All activations fp16 in gmem; f32 accum + f32 residual copies.
// ---------------------------------------------------------------------------

#define NPIX 4096
#define BATCH 4

// fp16 activations
__device__ __half g_inT[BATCH * NPIX * 8];
__device__ __half g_a1 [BATCH * NPIX * 64];
__device__ __half g_a2 [BATCH * NPIX * 128];
__device__ __half g_a3 [BATCH * NPIX * 256];
__device__ __half g_q  [BATCH * NPIX * 64];
__device__ __half g_k  [BATCH * NPIX * 64];
__device__ __half g_v  [BATCH * 512 * NPIX];          // channel-major [c][pix]
__device__ __half g_E  [(size_t)BATCH * NPIX * NPIX]; // 128 MB
__device__ __half g_t1 [BATCH * NPIX * 256];
__device__ __half g_t2 [BATCH * NPIX * 512];
__device__ __half g_a4 [BATCH * NPIX * 512];
// f32 residual sources
__device__ float g_a3f[BATCH * NPIX * 256];
__device__ float g_a4f[BATCH * NPIX * 512];
__device__ float g_sig[8];
// fp16 weights (spectral scale folded in for W1..W5)
__device__ __half g_W1h[64 * 8];
__device__ __half g_W2h[128 * 64];
__device__ __half g_W3h[256 * 128];
__device__ __half g_W4h[512 * 256];
__device__ __half g_W5h[1 * 512];
__device__ __half g_qW1h[32 * 256];
__device__ __half g_kW1h[32 * 256];
__device__ __half g_vW1h[256 * 256];
__device__ __half g_qW2h[64 * 512];
__device__ __half g_kW2h[64 * 512];
__device__ __half g_vW2h[512 * 512];

__device__ __forceinline__ uint32_t smem_u32(const void* p) {
    uint32_t a;
    asm("{ .reg .u64 t; cvta.to.shared.u64 t, %1; cvt.u32.u64 %0, t; }" : "=r"(a) : "l"(p));
    return a;
}

// ---------------------------------------------------------------------------
// cp.async one 128-row x 64-half tile into SW128 smem (128B rows, 8x16B chunks)
// K must be a multiple of 8 halfs (true for all call sites).
// ---------------------------------------------------------------------------
__device__ __forceinline__ void cpa_tile(uint32_t dstBase, const __half* src, int ld,
                                         int Rall, int r0, int K, int k0, int tid) {
    #pragma unroll
    for (int i = 0; i < 4; i++) {
        int e = tid + i * 256;
        int r = e >> 3, c = e & 7;
        int gr = r0 + r;
        uint32_t dst = dstBase + r * 128 + ((c ^ (r & 7)) << 4);
        bool ok = (gr < Rall) && (k0 + c * 8 < K);
        const __half* g = src + (ok ? ((size_t)gr * ld + k0 + c * 8) : 0);
        int bytes = ok ? 16 : 0;
        asm volatile("cp.async.cg.shared.global [%0], [%1], 16, %2;\n"
                     :: "r"(dst), "l"(g), "r"(bytes));
    }
}

// ---------------------------------------------------------------------------
// fp16 GEMM: C[m][n] = sum_k A[m,k]*B[n,k], A/B K-major fp16.
// Tile 128x128x64, 256 threads, dbl-buffered cp.async, ldmatrix fragments.
// EPI: 0 leaky(acc+bias[n]) -> fp16 (+f32 copy if WF32)
//      1 acc+bias[n] -> fp16
//      2 acc -> fp16 (energy)
//      3 gamma*acc + Resf32 -> fp16
//      4 acc+bias[n] -> fp16, transposed store C[n*NPIX + m]
//      5 leaky(acc+bias[n]) -> f32 (final layer)
// ---------------------------------------------------------------------------
template<int EPI, int WF32>
__global__ void __launch_bounds__(256, 2)
hgemm(const __half* __restrict__ A, const __half* __restrict__ B,
      __half* __restrict__ Ch, float* __restrict__ Cf,
      int Mall, int Nall, int K, int lda, int ldb, int ldc,
      size_t sA, size_t sB, size_t sC, size_t sCf, size_t sR,
      const float* __restrict__ bias, const float* __restrict__ gammaP,
      const float* __restrict__ Res)
{
    extern __shared__ char smem[];
    uint32_t sbase = smem_u32(smem);
    const uint32_t stageSz = 32768;   // A 16KB + B 16KB

    int tid = threadIdx.x, lane = tid & 31, wid = tid >> 5;
    int bz = blockIdx.z;
    A += sA * bz;  B += sB * bz;

    int m0 = blockIdx.x * 128;
    int n0 = blockIdx.y * 128;
    int wm = (wid & 3) * 32;
    int wn = (wid >> 2) * 64;

    float acc[2][8][4];
    #pragma unroll
    for (int a = 0; a < 2; a++)
        #pragma unroll
        for (int b = 0; b < 8; b++)
            #pragma unroll
            for (int c = 0; c < 4; c++) acc[a][b][c] = 0.f;

    int nkt = (K + 63) >> 6;

    cpa_tile(sbase, A, lda, Mall, m0, K, 0, tid);
    cpa_tile(sbase + 16384, B, ldb, Nall, n0, K, 0, tid);
    asm volatile("cp.async.commit_group;\n");

    for (int kt = 0; kt < nkt; kt++) {
        int buf = kt & 1;
        if (kt + 1 < nkt) {
            uint32_t nb = sbase + (buf ^ 1) * stageSz;
            cpa_tile(nb, A, lda, Mall, m0, K, (kt + 1) * 64, tid);
            cpa_tile(nb + 16384, B, ldb, Nall, n0, K, (kt + 1) * 64, tid);
            asm volatile("cp.async.commit_group;\n");
            asm volatile("cp.async.wait_group 1;\n");
        } else {
            asm volatile("cp.async.wait_group 0;\n");
        }
        __syncthreads();

        uint32_t Ab = sbase + buf * stageSz;
        uint32_t Bb = Ab + 16384;

        #pragma unroll
        for (int ks = 0; ks < 4; ks++) {
            int c0 = ks * 2;
            uint32_t af[2][4];
            #pragma unroll
            for (int mt = 0; mt < 2; mt++) {
                int lr = wm + mt * 16 + (lane & 15);
                int lc = c0 + (lane >> 4);
                uint32_t ad = Ab + lr * 128 + ((lc ^ (lr & 7)) << 4);
                asm volatile("ldmatrix.sync.aligned.m8n8.x4.shared.b16 {%0,%1,%2,%3}, [%4];\n"
                    : "=r"(af[mt][0]), "=r"(af[mt][1]), "=r"(af[mt][2]), "=r"(af[mt][3])
                    : "r"(ad));
            }
            uint32_t bf[8][2];
            #pragma unroll
            for (int j = 0; j < 4; j++) {
                int nb_ = wn + j * 16;
                int lr = nb_ + (lane & 7) + ((lane >> 4) << 3);
                int lc = c0 + ((lane >> 3) & 1);
                uint32_t bd = Bb + lr * 128 + ((lc ^ (lr & 7)) << 4);
                asm volatile("ldmatrix.sync.aligned.m8n8.x4.shared.b16 {%0,%1,%2,%3}, [%4];\n"
                    : "=r"(bf[2*j][0]), "=r"(bf[2*j][1]), "=r"(bf[2*j+1][0]), "=r"(bf[2*j+1][1])
                    : "r"(bd));
            }
            #pragma unroll
            for (int mt = 0; mt < 2; mt++)
                #pragma unroll
                for (int nt = 0; nt < 8; nt++)
                    asm volatile("mma.sync.aligned.m16n8k16.row.col.f32.f16.f16.f32 "
                        "{%0,%1,%2,%3}, {%4,%5,%6,%7}, {%8,%9}, {%0,%1,%2,%3};\n"
                        : "+f"(acc[mt][nt][0]), "+f"(acc[mt][nt][1]),
                          "+f"(acc[mt][nt][2]), "+f"(acc[mt][nt][3])
                        : "r"(af[mt][0]), "r"(af[mt][1]), "r"(af[mt][2]), "r"(af[mt][3]),
                          "r"(bf[nt][0]), "r"(bf[nt][1]));
        }
        __syncthreads();
    }

    // ---- epilogue
    __half* Cp = Ch + sC * bz;
    float*  Cfp = Cf + sCf * bz;
    const float* Rp = (EPI == 3) ? (Res + sR * bz) : nullptr;
    float gam = (EPI == 3) ? *gammaP : 0.f;
    int g = lane >> 2, tg = lane & 3;

    #pragma unroll
    for (int mt = 0; mt < 2; mt++)
    #pragma unroll
    for (int h = 0; h < 2; h++) {
        int row = m0 + wm + mt * 16 + g + h * 8;
        #pragma unroll
        for (int nt = 0; nt < 8; nt++) {
            int col = n0 + wn + nt * 8 + tg * 2;
            float v0 = acc[mt][nt][h * 2 + 0];
            float v1 = acc[mt][nt][h * 2 + 1];
            if (EPI == 0 || EPI == 5) {
                if (col < Nall)     { v0 += bias[col];     v0 = v0 > 0.f ? v0 : 0.1f * v0; }
                if (col + 1 < Nall) { v1 += bias[col + 1]; v1 = v1 > 0.f ? v1 : 0.1f * v1; }
            } else if (EPI == 1 || EPI == 4) {
                if (col < Nall)     v0 += bias[col];
                if (col + 1 < Nall) v1 += bias[col + 1];
            } else if (EPI == 3) {
                if (col < Nall) {
                    const float* rp = Rp + (size_t)row * ldc + col;
                    v0 = gam * v0 + rp[0];
                    v1 = gam * v1 + rp[1];
                }
            }
            if (EPI == 5) {
                if (col < Nall)     Cfp[(size_t)row * ldc + col]     = v0;
                if (col + 1 < Nall) Cfp[(size_t)row * ldc + col + 1] = v1;
            } else if (EPI == 4) {
                if (col < Nall)     Cp[(size_t)col * NPIX + row]       = __float2half(v0);
                if (col + 1 < Nall) Cp[(size_t)(col + 1) * NPIX + row] = __float2half(v1);
            } else {
                if (col < Nall) {  // Nall even at all fp16 call sites
                    *(__half2*)&Cp[(size_t)row * ldc + col] = __floats2half2_rn(v0, v1);
                    if (WF32)
                        *(float2*)&Cfp[(size_t)row * ldc + col] = make_float2(v0, v1);
                }
            }
        }
    }
}

// ---------------------------------------------------------------------------
// spectral norms (all 5, one block each)
// ---------------------------------------------------------------------------
__global__ void snorm_all(const float* __restrict__ W1, const float* __restrict__ u1,
                          const float* __restrict__ W2, const float* __restrict__ u2,
                          const float* __restrict__ W3, const float* __restrict__ u3,
                          const float* __restrict__ W4, const float* __restrict__ u4,
                          const float* __restrict__ W5, const float* __restrict__ u5,
                          float* __restrict__ sig)
{
    __shared__ float vs[512];
    __shared__ float us[512];
    __shared__ float red[256];
    __shared__ float red8[8];

    const float* W; const float* u; int O, C;
    switch (blockIdx.x) {
        case 0: W = W1; u = u1; O = 64;  C = 6;   break;
        case 1: W = W2; u = u2; O = 128; C = 64;  break;
        case 2: W = W3; u = u3; O = 256; C = 128; break;
        case 3: W = W4; u = u4; O = 512; C = 256; break;
        default: W = W5; u = u5; O = 1;  C = 512; break;
    }
    int t = threadIdx.x, lane = t & 31, wid = t >> 5;

    for (int o = t; o < O; o += 256) us[o] = u[o];
    __syncthreads();
    for (int c = t; c < C; c += 256) {
        float s = 0.f;
        #pragma unroll 4
        for (int o = 0; o < O; o++) s += W[(size_t)o * C + c] * us[o];
        vs[c] = s;
    }
    __syncthreads();
    float s = 0.f;
    for (int c = t; c < C; c += 256) s += vs[c] * vs[c];
    red[t] = s; __syncthreads();
    for (int off = 128; off > 0; off >>= 1) { if (t < off) red[t] += red[t + off]; __syncthreads(); }
    float vinv = 1.f / (sqrtf(red[0]) + 1e-12f);
    __syncthreads();
    for (int c = t; c < C; c += 256) vs[c] *= vinv;
    __syncthreads();
    float accq = 0.f;
    for (int o = wid; o < O; o += 8) {
        float tv = 0.f;
        for (int c = lane; c < C; c += 32) tv += W[(size_t)o * C + c] * vs[c];
        #pragma unroll
        for (int off = 16; off > 0; off >>= 1) tv += __shfl_xor_sync(0xffffffffu, tv, off);
        if (lane == 0) accq += tv * tv;
    }
    if (lane == 0) red8[wid] = accq;
    __syncthreads();
    if (t == 0) {
        float S = 0.f;
        #pragma unroll
        for (int w = 0; w < 8; w++) S += red8[w];
        float sigma = S / (sqrtf(S) + 1e-12f);
        sig[blockIdx.x] = 1.f / sigma;
    }
}

// ---------------------------------------------------------------------------
// weight conversion f32 -> fp16 (scaled by 1/sigma for W1..W5), K zero-padded
// ---------------------------------------------------------------------------
__global__ void wprep(const float* W1, const float* W2, const float* W3,
                      const float* W4, const float* W5,
                      const float* q1, const float* k1, const float* v1,
                      const float* q2, const float* k2, const float* v2,
                      const float* sig,
                      __half* o0, __half* o1, __half* o2, __half* o3, __half* o4,
                      __half* o5, __half* o6, __half* o7, __half* o8, __half* o9,
                      __half* o10)
{
    const float* src; __half* dst; int O, C, Cp; float s = 1.f;
    switch (blockIdx.x) {
        case 0:  src = W1; dst = o0;  O = 64;  C = 6;   Cp = 8;   s = sig[0]; break;
        case 1:  src = W2; dst = o1;  O = 128; C = 64;  Cp = 64;  s = sig[1]; break;
        case 2:  src = W3; dst = o2;  O = 256; C = 128; Cp = 128; s = sig[2]; break;
        case 3:  src = W4; dst = o3;  O = 512; C = 256; Cp = 256; s = sig[3]; break;
        case 4:  src = W5; dst = o4;  O = 1;   C = 512; Cp = 512; s = sig[4]; break;
        case 5:  src = q1; dst = o5;  O = 32;  C = 256; Cp = 256; break;
        case 6:  src = k1; dst = o6;  O = 32;  C = 256; Cp = 256; break;
        case 7:  src = v1; dst = o7;  O = 256; C = 256; Cp = 256; break;
        case 8:  src = q2; dst = o8;  O = 64;  C = 512; Cp = 512; break;
        case 9:  src = k2; dst = o9;  O = 64;  C = 512; Cp = 512; break;
        default: src = v2; dst = o10; O = 512; C = 512; Cp = 512; break;
    }
    int total = O * Cp;
    for (int i = blockIdx.y * 256 + threadIdx.x; i < total; i += 8 * 256) {
        int o = i / Cp, c = i % Cp;
        float v = (c < C) ? src[(size_t)o * C + c] * s : 0.f;
        dst[i] = __float2half(v);
    }
}

// ---------------------------------------------------------------------------
// input transpose: (B,6,64,64) f32 -> [b][pix][8] fp16 (2 pad channels)
// ---------------------------------------------------------------------------
__global__ void tin(const float* __restrict__ in, __half* __restrict__ out) {
    int b = blockIdx.y;
    int p = blockIdx.x * 256 + threadIdx.x;
    const float* s = in + (size_t)b * 6 * NPIX + p;
    __half h[8];
    #pragma unroll
    for (int c = 0; c < 6; c++) h[c] = __float2half(s[(size_t)c * NPIX]);
    h[6] = __float2half(0.f);
    h[7] = __float2half(0.f);
    *(uint4*)(out + ((size_t)b * NPIX + p) * 8) = *(uint4*)h;
}

// ---------------------------------------------------------------------------
// fp16 row softmax (rows of 4096), f32 math, one block per row
// ---------------------------------------------------------------------------
__global__ void softmax_h(__half* __restrict__ E) {
    __shared__ float rm[256], rs[256];
    __half2* row = (__half2*)(E + (size_t)blockIdx.x * NPIX);
    int t = threadIdx.x;

    float mx = -3.0e38f, sm = 0.f;
    #pragma unroll
    for (int i = t; i < NPIX / 2; i += 256) {
        float2 v = __half22float2(row[i]);
        float m2 = fmaxf(v.x, v.y);
        if (m2 > mx) { sm *= __expf(mx - m2); mx = m2; }
        sm += __expf(v.x - mx) + __expf(v.y - mx);
    }
    rm[t] = mx; rs[t] = sm; __syncthreads();
    for (int off = 128; off > 0; off >>= 1) {
        if (t < off) {
            float m1 = rm[t], m2 = rm[t + off];
            float M = fmaxf(m1, m2);
            rs[t] = rs[t] * __expf(m1 - M) + rs[t + off] * __expf(m2 - M);
            rm[t] = M;
        }
        __syncthreads();
    }
    float M = rm[0];
    float inv = 1.f / rs[0];

    #pragma unroll
    for (int i = t; i < NPIX / 2; i += 256) {
        float2 v = __half22float2(row[i]);
        row[i] = __floats2half2_rn(__expf(v.x - M) * inv, __expf(v.y - M) * inv);
    }
}

// ---------------------------------------------------------------------------
// kernel_launch
// ---------------------------------------------------------------------------
extern "C" void kernel_launch(void* const* d_in, const int* in_sizes, int n_in,
                              void* d_out, int out_size)
{
    const float* inp  = (const float*)d_in[0];
    const float* W1 = (const float*)d_in[1];  const float* b1 = (const float*)d_in[2];  const float* u1 = (const float*)d_in[3];
    const float* W2 = (const float*)d_in[4];  const float* b2 = (const float*)d_in[5];  const float* u2 = (const float*)d_in[6];
    const float* W3 = (const float*)d_in[7];  const float* b3 = (const float*)d_in[8];  const float* u3 = (const float*)d_in[9];
    const float* W4 = (const float*)d_in[10]; const float* b4 = (const float*)d_in[11]; const float* u4 = (const float*)d_in[12];
    const float* W5 = (const float*)d_in[13]; const float* b5 = (const float*)d_in[14]; const float* u5 = (const float*)d_in[15];
    const float* a1qW = (const float*)d_in[16]; const float* a1qb = (const float*)d_in[17];
    const float* a1kW = (const float*)d_in[18]; const float* a1kb = (const float*)d_in[19];
    const float* a1vW = (const float*)d_in[20]; const float* a1vb = (const float*)d_in[21];
    const float* a1g  = (const float*)d_in[22];
    const float* a2qW = (const float*)d_in[23]; const float* a2qb = (const float*)d_in[24];
    const float* a2kW = (const float*)d_in[25]; const float* a2kb = (const float*)d_in[26];
    const float* a2vW = (const float*)d_in[27]; const float* a2vb = (const float*)d_in[28];
    const float* a2g  = (const float*)d_in[29];

    __half *inTh, *a1h, *a2h, *a3h, *qh, *kh, *vh, *Eh, *t1h, *t2h, *a4h;
    __half *W1h, *W2h, *W3h, *W4h, *W5h, *qW1h, *kW1h, *vW1h, *qW2h, *kW2h, *vW2h;
    float *a3f, *a4f, *sig;
    cudaGetSymbolAddress((void**)&inTh, g_inT);
    cudaGetSymbolAddress((void**)&a1h, g_a1);
    cudaGetSymbolAddress((void**)&a2h, g_a2);
    cudaGetSymbolAddress((void**)&a3h, g_a3);
    cudaGetSymbolAddress((void**)&qh,  g_q);
    cudaGetSymbolAddress((void**)&kh,  g_k);
    cudaGetSymbolAddress((void**)&vh,  g_v);
    cudaGetSymbolAddress((void**)&Eh,  g_E);
    cudaGetSymbolAddress((void**)&t1h, g_t1);
    cudaGetSymbolAddress((void**)&t2h, g_t2);
    cudaGetSymbolAddress((void**)&a4h, g_a4);
    cudaGetSymbolAddress((void**)&a3f, g_a3f);
    cudaGetSymbolAddress((void**)&a4f, g_a4f);
    cudaGetSymbolAddress((void**)&sig, g_sig);
    cudaGetSymbolAddress((void**)&W1h, g_W1h);
    cudaGetSymbolAddress((void**)&W2h, g_W2h);
    cudaGetSymbolAddress((void**)&W3h, g_W3h);
    cudaGetSymbolAddress((void**)&W4h, g_W4h);
    cudaGetSymbolAddress((void**)&W5h, g_W5h);
    cudaGetSymbolAddress((void**)&qW1h, g_qW1h);
    cudaGetSymbolAddress((void**)&kW1h, g_kW1h);
    cudaGetSymbolAddress((void**)&vW1h, g_vW1h);
    cudaGetSymbolAddress((void**)&qW2h, g_qW2h);
    cudaGetSymbolAddress((void**)&kW2h, g_kW2h);
    cudaGetSymbolAddress((void**)&vW2h, g_vW2h);

    const int SMEMSZ = 65536;
    cudaFuncSetAttribute(hgemm<0,0>, cudaFuncAttributeMaxDynamicSharedMemorySize, SMEMSZ);
    cudaFuncSetAttribute(hgemm<0,1>, cudaFuncAttributeMaxDynamicSharedMemorySize, SMEMSZ);
    cudaFuncSetAttribute(hgemm<1,0>, cudaFuncAttributeMaxDynamicSharedMemorySize, SMEMSZ);
    cudaFuncSetAttribute(hgemm<2,0>, cudaFuncAttributeMaxDynamicSharedMemorySize, SMEMSZ);
    cudaFuncSetAttribute(hgemm<3,0>, cudaFuncAttributeMaxDynamicSharedMemorySize, SMEMSZ);
    cudaFuncSetAttribute(hgemm<4,0>, cudaFuncAttributeMaxDynamicSharedMemorySize, SMEMSZ);
    cudaFuncSetAttribute(hgemm<5,0>, cudaFuncAttributeMaxDynamicSharedMemorySize, SMEMSZ);

    const size_t NP = NPIX;
    const size_t NN = NP * NP;
    auto gd = [&](int Nn) { return dim3(NPIX / 128, (Nn + 127) / 128, BATCH); };

    snorm_all<<<5, 256>>>(W1, u1, W2, u2, W3, u3, W4, u4, W5, u5, sig);
    wprep<<<dim3(11, 8), 256>>>(W1, W2, W3, W4, W5, a1qW, a1kW, a1vW, a2qW, a2kW, a2vW,
                                sig, W1h, W2h, W3h, W4h, W5h,
                                qW1h, kW1h, vW1h, qW2h, kW2h, vW2h);
    tin<<<dim3(16, BATCH), 256>>>(inp, inTh);

    // conv1/2/3
    hgemm<0,0><<<gd(64), 256, SMEMSZ>>>(inTh, W1h, a1h, nullptr, NPIX, 64, 8, 8, 8, 64,
        NP * 8, 0, NP * 64, 0, 0, b1, nullptr, nullptr);
    hgemm<0,0><<<gd(128), 256, SMEMSZ>>>(a1h, W2h, a2h, nullptr, NPIX, 128, 64, 64, 64, 128,
        NP * 64, 0, NP * 128, 0, 0, b2, nullptr, nullptr);
    hgemm<0,1><<<gd(256), 256, SMEMSZ>>>(a2h, W3h, a3h, a3f, NPIX, 256, 128, 128, 128, 256,
        NP * 128, 0, NP * 256, NP * 256, 0, b3, nullptr, nullptr);

    // attention 1 (C=256, Cq=32)
    hgemm<1,0><<<gd(32), 256, SMEMSZ>>>(a3h, qW1h, qh, nullptr, NPIX, 32, 256, 256, 256, 32,
        NP * 256, 0, NP * 32, 0, 0, a1qb, nullptr, nullptr);
    hgemm<1,0><<<gd(32), 256, SMEMSZ>>>(a3h, kW1h, kh, nullptr, NPIX, 32, 256, 256, 256, 32,
        NP * 256, 0, NP * 32, 0, 0, a1kb, nullptr, nullptr);
    hgemm<4,0><<<gd(256), 256, SMEMSZ>>>(a3h, vW1h, vh, nullptr, NPIX, 256, 256, 256, 256, NPIX,
        NP * 256, 0, 256 * NP, 0, 0, a1vb, nullptr, nullptr);
    hgemm<2,0><<<gd(4096), 256, SMEMSZ>>>(qh, kh, Eh, nullptr, NPIX, 4096, 32, 32, 32, 4096,
        NP * 32, NP * 32, NN, 0, 0, nullptr, nullptr, nullptr);
    softmax_h<<<BATCH * NPIX, 256>>>(Eh);
    hgemm<3,0><<<gd(256), 256, SMEMSZ>>>(Eh, vh, t1h, nullptr, NPIX, 256, 4096, 4096, 4096, 256,
        NN, 256 * NP, NP * 256, 0, NP * 256, nullptr, a1g, a3f);

    // conv4
    hgemm<0,1><<<gd(512), 256, SMEMSZ>>>(t1h, W4h, a4h, a4f, NPIX, 512, 256, 256, 256, 512,
        NP * 256, 0, NP * 512, NP * 512, 0, b4, nullptr, nullptr);

    // attention 2 (C=512, Cq=64)
    hgemm<1,0><<<gd(64), 256, SMEMSZ>>>(a4h, qW2h, qh, nullptr, NPIX, 64, 512, 512, 512, 64,
        NP * 512, 0, NP * 64, 0, 0, a2qb, nullptr, nullptr);
    hgemm<1,0><<<gd(64), 256, SMEMSZ>>>(a4h, kW2h, kh, nullptr, NPIX, 64, 512, 512, 512, 64,
        NP * 512, 0, NP * 64, 0, 0, a2kb, nullptr, nullptr);
    hgemm<4,0><<<gd(512), 256, SMEMSZ>>>(a4h, vW2h, vh, nullptr, NPIX, 512, 512, 512, 512, NPIX,
        NP * 512, 0, 512 * NP, 0, 0, a2vb, nullptr, nullptr);
    hgemm<2,0><<<gd(4096), 256, SMEMSZ>>>(qh, kh, Eh, nullptr, NPIX, 4096, 64, 64, 64, 4096,
        NP * 64, NP * 64, NN, 0, 0, nullptr, nullptr, nullptr);
    softmax_h<<<BATCH * NPIX, 256>>>(Eh);
    hgemm<3,0><<<gd(512), 256, SMEMSZ>>>(Eh, vh, t2h, nullptr, NPIX, 512, 4096, 4096, 4096, 512,
        NN, 512 * NP, NP * 512, 0, NP * 512, nullptr, a2g, a4f);

    // conv5 -> f32 output (B, 4096)
    hgemm<5,0><<<gd(1), 256, SMEMSZ>>>(t2h, W5h, nullptr, (float*)d_out, NPIX, 1, 512, 512, 512, 1,
        NP * 512, 0, 0, NP, 0, b5, nullptr, nullptr);
}